// round 15
// baseline (speedup 1.0000x reference)
#include <cuda_runtime.h>
#include <cuda_fp16.h>
#include <cstdint>
#include <math.h>

#define B_DIM 64
#define S_DIM 2048
#define D_DIM 512

#define BLK_S 128
#define NTHREADS 256
#define NMACRO 32            // 4 ei * 8 kt (k-tile = 64)
#define STG_BYTES 49152      // A fp32 32KB + B fp16 16KB
#define CONST_OFF 24576      // words (= 2 * STG_BYTES / 4)
#define SMEM_WORDS (CONST_OFF + 1664)    // 104960 B -> 2 CTAs/SM

// scratch (no device mallocs; __device__ globals are the sanctioned path)
__device__ uint32_t g_w16[NMACRO * 4096];   // W fp16, fragment-ordered
__device__ float    g_qpb[B_DIM * D_DIM];   // q + Wq_b + Wr_b

// ---------------------------------------------------------------------------
// prep: [0,256): W -> fragment-ordered fp16 pairs.  [256,1280): q projection.
// ---------------------------------------------------------------------------
__global__ void prep_kernel(const float* __restrict__ Wr_w,
                            const float* __restrict__ query,
                            const float* __restrict__ Wq_w,
                            const float* __restrict__ Wq_b,
                            const float* __restrict__ Wr_b) {
    if (blockIdx.x < 256) {
        int o = blockIdx.x * 256 + threadIdx.x;
        #pragma unroll
        for (int it = 0; it < 2; it++, o += 65536) {
            const int g = o >> 12, rem = o & 4095;
            const int c = rem >> 2, w = rem & 3;
            const int lane = c & 31, t = c >> 5;
            const int j = t & 3, we = (t >> 2) & 1, ks = t >> 3;
            const int ei = g >> 3, kt = g & 7;
            const int tn = j * 2 + (w >> 1);
            const int e = ei * 128 + we * 64 + tn * 8 + (lane >> 2);
            const int k = kt * 64 + ks * 16 + 2 * (lane & 3) + (w & 1) * 8;
            __half2 h = __floats2half2_rn(Wr_w[e * D_DIM + k], Wr_w[e * D_DIM + k + 1]);
            g_w16[o] = *reinterpret_cast<uint32_t*>(&h);
        }
    } else {
        __shared__ float qs[D_DIM];
        const int id2 = blockIdx.x - 256;
        const int b = id2 & 63;
        const int eblk = id2 >> 6;
        const int tid = threadIdx.x, lane = tid & 31, w = tid >> 5;
        for (int i = tid; i < D_DIM; i += 256) qs[i] = query[(size_t)b * D_DIM + i];
        __syncthreads();
        const int e0 = eblk * 32 + w * 4;
        #pragma unroll
        for (int k = 0; k < 4; k++) {
            const int e = e0 + k;
            const float* wr = Wq_w + (size_t)e * D_DIM;
            float s = 0.f;
            #pragma unroll
            for (int d = lane; d < D_DIM; d += 32) s += qs[d] * wr[d];
            #pragma unroll
            for (int o = 16; o; o >>= 1) s += __shfl_xor_sync(0xffffffffu, s, o);
            if (lane == 0) g_qpb[b * D_DIM + e] = s + Wq_b[e] + Wr_b[e];
        }
    }
}

// ---------------------------------------------------------------------------
// helpers
// ---------------------------------------------------------------------------
__device__ __forceinline__ void cp16(void* dst, const void* src) {
    unsigned s = (unsigned)__cvta_generic_to_shared(dst);
    asm volatile("cp.async.cg.shared.global [%0], [%1], 16;"
                 :: "r"(s), "l"(src) : "memory");
}
__device__ __forceinline__ float tanha(float x) {
    float y;
    asm("tanh.approx.f32 %0, %1;" : "=f"(y) : "f"(x));
    return y;
}
__device__ __forceinline__ unsigned cvt_pair(uint2 t) {
    __half2 h = __floats2half2_rn(__uint_as_float(t.x), __uint_as_float(t.y));
    return *reinterpret_cast<unsigned*>(&h);
}

#define SM_BIAS(i) sm[CONST_OFF + (i)]
#define SM_QPB(i)  sm[CONST_OFF + 512 + (i)]
#define SM_V(i)    sm[CONST_OFF + 1024 + (i)]
#define SM_L(i)    sm[CONST_OFF + 1536 + (i)]

// ---------------------------------------------------------------------------
// main: fp16 m16n8k16 HMMA. A staged fp32 (cp.async direct), cvt in fragment
// path. B fp16 staged. 2-stage ring, 1 barrier/macro, half-slice B pipeline.
// R15: slice-0 fragment loads issued BEFORE next-stage prefetch clump, so the
// first MMA burst of each macro is not delayed by cp.async issue slots.
// ---------------------------------------------------------------------------
__global__ void __launch_bounds__(NTHREADS, 2)
attn_main(const float* __restrict__ ref,
          const float* __restrict__ Wr_b,
          const float* __restrict__ value,
          float* __restrict__ out_r,
          float* __restrict__ out_logits)
{
    extern __shared__ float sm[];
    char* smc = reinterpret_cast<char*>(sm);
    const int tid    = threadIdx.x;
    const int lane   = tid & 31;
    const int warp   = tid >> 5;
    const int warp_s = warp & 3;
    const int warp_e = warp >> 2;
    const int b  = blockIdx.y;
    const int s0 = blockIdx.x * BLK_S;

    const float* aG32 = ref + ((size_t)b * S_DIM + s0) * D_DIM;
    float* outr_b = out_r + (size_t)b * D_DIM * S_DIM;

    auto prefetch = [&](int g, int slot) {
        uint2* sa = reinterpret_cast<uint2*>(smc + slot * STG_BYTES);
        uint32_t* sb = reinterpret_cast<uint32_t*>(smc + slot * STG_BYTES + 32768);
        const float* asrc = aG32 + (g & 7) * 64;
        const uint32_t* bsrc = g_w16 + (size_t)g * 4096;
        #pragma unroll
        for (int i = 0; i < 8; i++) {
            const int c = tid + i * 256;
            const int row = c >> 4, u = c & 15;
            const int up = u ^ ((row & 3) << 1);
            cp16(sa + row * 32 + up * 2, asrc + (size_t)row * D_DIM + u * 4);
        }
        #pragma unroll
        for (int i = 0; i < 4; i++)
            cp16(sb + (tid + i * 256) * 4, bsrc + (tid + i * 256) * 4);
        asm volatile("cp.async.commit_group;" ::: "memory");
    };

    prefetch(0, 0);

    // epilogue constants
    for (int i = tid; i < D_DIM; i += NTHREADS) {
        SM_BIAS(i) = Wr_b[i];
        SM_QPB(i)  = g_qpb[b * D_DIM + i];
        SM_V(i)    = value[i];
    }
    if (tid < BLK_S) SM_L(tid) = 0.0f;

    const int rbase = warp_s * 32 + (lane >> 2);
    const int plo   = lane & 3;
    const int bbase = warp_e * 512 + lane * 4;   // words within B ks-block

    float acc[2][8][4];
    #pragma unroll
    for (int tm = 0; tm < 2; tm++)
        #pragma unroll
        for (int tn = 0; tn < 8; tn++)
            #pragma unroll
            for (int i = 0; i < 4; i++) acc[tm][tn][i] = 0.f;

    unsigned af[2][2][4];
    uint4    bq[2][2];    // ping-pong half-slice B fragments

    #pragma unroll 1
    for (int g = 0; g < NMACRO; g++) {
        asm volatile("cp.async.wait_group 0;" ::: "memory");
        __syncthreads();

        const int slot = g & 1;
        const uint2* sa = reinterpret_cast<const uint2*>(smc + slot * STG_BYTES);
        const uint32_t* sb =
            reinterpret_cast<const uint32_t*>(smc + slot * STG_BYTES + 32768);

        auto loadA = [&](int buf, int ks) {
            const int p = ks * 8 + plo;
            #pragma unroll
            for (int tm = 0; tm < 2; tm++) {
                const int r0 = rbase + tm * 16;
                const int sw = (r0 & 3) << 2;
                af[buf][tm][0] = cvt_pair(sa[ r0      * 32 + ( p      ^ sw)]);
                af[buf][tm][1] = cvt_pair(sa[(r0 + 8) * 32 + ( p      ^ sw)]);
                af[buf][tm][2] = cvt_pair(sa[ r0      * 32 + ((p + 4) ^ sw)]);
                af[buf][tm][3] = cvt_pair(sa[(r0 + 8) * 32 + ((p + 4) ^ sw)]);
            }
        };
        auto loadB = [&](int buf, int i) {
            const uint32_t* p = sb + (i >> 1) * 1024 + (i & 1) * 256 + bbase;
            bq[buf][0] = *reinterpret_cast<const uint4*>(p);
            bq[buf][1] = *reinterpret_cast<const uint4*>(p + 128);
        };

        // critical path first: slice-0 fragments for THIS macro
        loadB(0, 0);
        loadA(0, 0);

        // then the next-stage prefetch clump (has a full macro of slack)
        if (g + 1 < NMACRO) prefetch(g + 1, (g + 1) & 1);

        // 8 half-slices; prefetch half i+1 before MMAs of half i
        #pragma unroll
        for (int i = 0; i < 8; i++) {
            const int ks = i >> 1, half = i & 1, buf = i & 1;
            if (i < 7) loadB(buf ^ 1, i + 1);
            if (half == 1 && ks < 3) loadA((ks & 1) ^ 1, ks + 1);
            const int ab = ks & 1;
            #pragma unroll
            for (int tm = 0; tm < 2; tm++)
                #pragma unroll
                for (int jj = 0; jj < 2; jj++) {
                    const int tn0 = (half * 2 + jj) * 2;
                    asm volatile(
                        "mma.sync.aligned.m16n8k16.row.col.f32.f16.f16.f32 "
                        "{%0,%1,%2,%3}, {%4,%5,%6,%7}, {%8,%9}, {%0,%1,%2,%3};"
                        : "+f"(acc[tm][tn0][0]), "+f"(acc[tm][tn0][1]),
                          "+f"(acc[tm][tn0][2]), "+f"(acc[tm][tn0][3])
                        : "r"(af[ab][tm][0]), "r"(af[ab][tm][1]),
                          "r"(af[ab][tm][2]), "r"(af[ab][tm][3]),
                          "r"(bq[buf][jj].x), "r"(bq[buf][jj].y));
                    asm volatile(
                        "mma.sync.aligned.m16n8k16.row.col.f32.f16.f16.f32 "
                        "{%0,%1,%2,%3}, {%4,%5,%6,%7}, {%8,%9}, {%0,%1,%2,%3};"
                        : "+f"(acc[tm][tn0 + 1][0]), "+f"(acc[tm][tn0 + 1][1]),
                          "+f"(acc[tm][tn0 + 1][2]), "+f"(acc[tm][tn0 + 1][3])
                        : "r"(af[ab][tm][0]), "r"(af[ab][tm][1]),
                          "r"(af[ab][tm][2]), "r"(af[ab][tm][3]),
                          "r"(bq[buf][jj].z), "r"(bq[buf][jj].w));
                }
        }

        // -------- epilogue at each ei boundary --------
        if ((g & 7) == 7) {
            const int ei = g >> 3;
            float lp[2][2] = {{0.f, 0.f}, {0.f, 0.f}};
            const int sg0 = s0 + warp_s * 32 + (lane >> 2);
            #pragma unroll
            for (int tm = 0; tm < 2; tm++) {
                const int srow = sg0 + tm * 16;
                #pragma unroll
                for (int tn = 0; tn < 8; tn++) {
                    const int e = ei * 128 + warp_e * 64 + tn * 8 + 2 * (lane & 3);
                    const float b0v = SM_BIAS(e), b1v = SM_BIAS(e + 1);
                    const float a0 = acc[tm][tn][0], a1 = acc[tm][tn][1];
                    const float a2 = acc[tm][tn][2], a3 = acc[tm][tn][3];
                    __stwt(&outr_b[(size_t)e       * S_DIM + srow],     a0 + b0v);
                    __stwt(&outr_b[(size_t)(e + 1) * S_DIM + srow],     a1 + b1v);
                    __stwt(&outr_b[(size_t)e       * S_DIM + srow + 8], a2 + b0v);
                    __stwt(&outr_b[(size_t)(e + 1) * S_DIM + srow + 8], a3 + b1v);
                    const float q0 = SM_QPB(e), q1 = SM_QPB(e + 1);
                    const float v0 = SM_V(e), v1 = SM_V(e + 1);
                    lp[tm][0] += tanha(q0 + a0) * v0 + tanha(q1 + a1) * v1;
                    lp[tm][1] += tanha(q0 + a2) * v0 + tanha(q1 + a3) * v1;
                    acc[tm][tn][0] = 0.f; acc[tm][tn][1] = 0.f;
                    acc[tm][tn][2] = 0.f; acc[tm][tn][3] = 0.f;
                }
            }
            #pragma unroll
            for (int tm = 0; tm < 2; tm++)
                #pragma unroll
                for (int h = 0; h < 2; h++) {
                    float v = lp[tm][h];
                    v += __shfl_xor_sync(0xffffffffu, v, 1);
                    v += __shfl_xor_sync(0xffffffffu, v, 2);
                    if ((lane & 3) == 0)
                        atomicAdd(&SM_L(warp_s * 32 + tm * 16 + h * 8 + (lane >> 2)), v);
                }
        }
    }

    __syncthreads();
    if (tid < BLK_S)
        __stwt(&out_logits[(size_t)b * S_DIM + s0 + tid], 10.0f * tanha(SM_L(tid)));
}

// ---------------------------------------------------------------------------
// launch
// ---------------------------------------------------------------------------
extern "C" void kernel_launch(void* const* d_in, const int* in_sizes, int n_in,
                              void* d_out, int out_size) {
    const float* query = (const float*)d_in[0];
    const float* ref   = (const float*)d_in[1];
    const float* Wq_w  = (const float*)d_in[2];
    const float* Wq_b  = (const float*)d_in[3];
    const float* Wr_w  = (const float*)d_in[4];
    const float* Wr_b  = (const float*)d_in[5];
    const float* value = (const float*)d_in[6];
    (void)in_sizes; (void)n_in; (void)out_size;

    float* out        = (float*)d_out;
    float* out_r      = out;                                   // [B, D, S]
    float* out_logits = out + (size_t)B_DIM * D_DIM * S_DIM;   // [B, S]

    prep_kernel<<<1280, 256>>>(Wr_w, query, Wq_w, Wq_b, Wr_b);

    const size_t smem = SMEM_WORDS * sizeof(float);
    cudaFuncSetAttribute(attn_main, cudaFuncAttributeMaxDynamicSharedMemorySize,
                         (int)smem);
    dim3 grid(S_DIM / BLK_S, B_DIM);
    attn_main<<<grid, NTHREADS, smem>>>(ref, Wr_b, value, out_r, out_logits);
}

// round 16
// speedup vs baseline: 1.0098x; 1.0098x over previous
#include <cuda_runtime.h>
#include <cuda_fp16.h>
#include <cstdint>
#include <math.h>

#define B_DIM 64
#define S_DIM 2048
#define D_DIM 512

#define BLK_S 128
#define NTHREADS 256
#define NMACRO 32            // 4 ei * 8 kt (k-tile = 64)
#define STG_BYTES 49152      // A fp32 32KB + B fp16 16KB
#define CONST_OFF 24576      // words (= 2 * STG_BYTES / 4)
#define SMEM_WORDS (CONST_OFF + 1664)    // 104960 B -> 2 CTAs/SM

// scratch (no device mallocs; __device__ globals are the sanctioned path)
__device__ uint32_t g_w16[NMACRO * 4096];   // W fp16, fragment-ordered
__device__ float    g_qpb[B_DIM * D_DIM];   // q + Wq_b + Wr_b

// ---------------------------------------------------------------------------
// prep: [0,256): W -> fragment-ordered fp16 pairs.  [256,1280): q projection.
// ---------------------------------------------------------------------------
__global__ void prep_kernel(const float* __restrict__ Wr_w,
                            const float* __restrict__ query,
                            const float* __restrict__ Wq_w,
                            const float* __restrict__ Wq_b,
                            const float* __restrict__ Wr_b) {
    if (blockIdx.x < 256) {
        int o = blockIdx.x * 256 + threadIdx.x;
        #pragma unroll
        for (int it = 0; it < 2; it++, o += 65536) {
            const int g = o >> 12, rem = o & 4095;
            const int c = rem >> 2, w = rem & 3;
            const int lane = c & 31, t = c >> 5;
            const int j = t & 3, we = (t >> 2) & 1, ks = t >> 3;
            const int ei = g >> 3, kt = g & 7;
            const int tn = j * 2 + (w >> 1);
            const int e = ei * 128 + we * 64 + tn * 8 + (lane >> 2);
            const int k = kt * 64 + ks * 16 + 2 * (lane & 3) + (w & 1) * 8;
            __half2 h = __floats2half2_rn(Wr_w[e * D_DIM + k], Wr_w[e * D_DIM + k + 1]);
            g_w16[o] = *reinterpret_cast<uint32_t*>(&h);
        }
    } else {
        __shared__ float qs[D_DIM];
        const int id2 = blockIdx.x - 256;
        const int b = id2 & 63;
        const int eblk = id2 >> 6;
        const int tid = threadIdx.x, lane = tid & 31, w = tid >> 5;
        for (int i = tid; i < D_DIM; i += 256) qs[i] = query[(size_t)b * D_DIM + i];
        __syncthreads();
        const int e0 = eblk * 32 + w * 4;
        #pragma unroll
        for (int k = 0; k < 4; k++) {
            const int e = e0 + k;
            const float* wr = Wq_w + (size_t)e * D_DIM;
            float s = 0.f;
            #pragma unroll
            for (int d = lane; d < D_DIM; d += 32) s += qs[d] * wr[d];
            #pragma unroll
            for (int o = 16; o; o >>= 1) s += __shfl_xor_sync(0xffffffffu, s, o);
            if (lane == 0) g_qpb[b * D_DIM + e] = s + Wq_b[e] + Wr_b[e];
        }
    }
}

// ---------------------------------------------------------------------------
// helpers
// ---------------------------------------------------------------------------
__device__ __forceinline__ void cp16(void* dst, const void* src) {
    unsigned s = (unsigned)__cvta_generic_to_shared(dst);
    asm volatile("cp.async.cg.shared.global [%0], [%1], 16;"
                 :: "r"(s), "l"(src) : "memory");
}
__device__ __forceinline__ float tanha(float x) {
    float y;
    asm("tanh.approx.f32 %0, %1;" : "=f"(y) : "f"(x));
    return y;
}
__device__ __forceinline__ unsigned cvt_pair(uint2 t) {
    __half2 h = __floats2half2_rn(__uint_as_float(t.x), __uint_as_float(t.y));
    return *reinterpret_cast<unsigned*>(&h);
}

#define SM_BIAS(i) sm[CONST_OFF + (i)]
#define SM_QPB(i)  sm[CONST_OFF + 512 + (i)]
#define SM_V(i)    sm[CONST_OFF + 1024 + (i)]
#define SM_L(i)    sm[CONST_OFF + 1536 + (i)]

// ---------------------------------------------------------------------------
// main: fp16 m16n8k16 HMMA. A staged as fp32 (cp.async direct from ref),
// converted to fp16 in the fragment path (LDS.64 + cvt.f16x2). B fp16 staged.
// 2-stage ring, 1 barrier/macro, half-slice-pipelined B fragments.
// ---------------------------------------------------------------------------
__global__ void __launch_bounds__(NTHREADS, 2)
attn_main(const float* __restrict__ ref,
          const float* __restrict__ Wr_b,
          const float* __restrict__ value,
          float* __restrict__ out_r,
          float* __restrict__ out_logits)
{
    extern __shared__ float sm[];
    char* smc = reinterpret_cast<char*>(sm);
    const int tid    = threadIdx.x;
    const int lane   = tid & 31;
    const int warp   = tid >> 5;
    const int warp_s = warp & 3;
    const int warp_e = warp >> 2;
    const int b  = blockIdx.y;
    const int s0 = blockIdx.x * BLK_S;

    const float* aG32 = ref + ((size_t)b * S_DIM + s0) * D_DIM;
    float* outr_b = out_r + (size_t)b * D_DIM * S_DIM;

    auto prefetch = [&](int g, int slot) {
        uint2* sa = reinterpret_cast<uint2*>(smc + slot * STG_BYTES);
        uint32_t* sb = reinterpret_cast<uint32_t*>(smc + slot * STG_BYTES + 32768);
        const float* asrc = aG32 + (g & 7) * 64;
        const uint32_t* bsrc = g_w16 + (size_t)g * 4096;
        #pragma unroll
        for (int i = 0; i < 8; i++) {
            const int c = tid + i * 256;
            const int row = c >> 4, u = c & 15;
            const int up = u ^ ((row & 3) << 1);
            cp16(sa + row * 32 + up * 2, asrc + (size_t)row * D_DIM + u * 4);
        }
        #pragma unroll
        for (int i = 0; i < 4; i++)
            cp16(sb + (tid + i * 256) * 4, bsrc + (tid + i * 256) * 4);
        asm volatile("cp.async.commit_group;" ::: "memory");
    };

    prefetch(0, 0);

    // epilogue constants
    for (int i = tid; i < D_DIM; i += NTHREADS) {
        SM_BIAS(i) = Wr_b[i];
        SM_QPB(i)  = g_qpb[b * D_DIM + i];
        SM_V(i)    = value[i];
    }
    if (tid < BLK_S) SM_L(tid) = 0.0f;

    const int rbase = warp_s * 32 + (lane >> 2);
    const int plo   = lane & 3;
    const int bbase = warp_e * 512 + lane * 4;   // words within B ks-block

    float acc[2][8][4];
    #pragma unroll
    for (int tm = 0; tm < 2; tm++)
        #pragma unroll
        for (int tn = 0; tn < 8; tn++)
            #pragma unroll
            for (int i = 0; i < 4; i++) acc[tm][tn][i] = 0.f;

    unsigned af[2][2][4];
    uint4    bq[2][2];    // ping-pong half-slice B fragments

    #pragma unroll 1
    for (int g = 0; g < NMACRO; g++) {
        asm volatile("cp.async.wait_group 0;" ::: "memory");
        __syncthreads();

        if (g + 1 < NMACRO) prefetch(g + 1, (g + 1) & 1);

        const int slot = g & 1;
        const uint2* sa = reinterpret_cast<const uint2*>(smc + slot * STG_BYTES);
        const uint32_t* sb =
            reinterpret_cast<const uint32_t*>(smc + slot * STG_BYTES + 32768);

        auto loadA = [&](int buf, int ks) {
            const int p = ks * 8 + plo;
            #pragma unroll
            for (int tm = 0; tm < 2; tm++) {
                const int r0 = rbase + tm * 16;
                const int sw = (r0 & 3) << 2;
                af[buf][tm][0] = cvt_pair(sa[ r0      * 32 + ( p      ^ sw)]);
                af[buf][tm][1] = cvt_pair(sa[(r0 + 8) * 32 + ( p      ^ sw)]);
                af[buf][tm][2] = cvt_pair(sa[ r0      * 32 + ((p + 4) ^ sw)]);
                af[buf][tm][3] = cvt_pair(sa[(r0 + 8) * 32 + ((p + 4) ^ sw)]);
            }
        };
        // half-slice B loader: i = ks*2 + half
        auto loadB = [&](int buf, int i) {
            const uint32_t* p = sb + (i >> 1) * 1024 + (i & 1) * 256 + bbase;
            bq[buf][0] = *reinterpret_cast<const uint4*>(p);
            bq[buf][1] = *reinterpret_cast<const uint4*>(p + 128);
        };

        loadA(0, 0);
        loadB(0, 0);

        // 8 half-slices; prefetch half i+1 before MMAs of half i
        #pragma unroll
        for (int i = 0; i < 8; i++) {
            const int ks = i >> 1, half = i & 1, buf = i & 1;
            if (i < 7) loadB(buf ^ 1, i + 1);
            if (half == 1 && ks < 3) loadA((ks & 1) ^ 1, ks + 1);
            const int ab = ks & 1;
            #pragma unroll
            for (int tm = 0; tm < 2; tm++)
                #pragma unroll
                for (int jj = 0; jj < 2; jj++) {
                    const int tn0 = (half * 2 + jj) * 2;
                    asm volatile(
                        "mma.sync.aligned.m16n8k16.row.col.f32.f16.f16.f32 "
                        "{%0,%1,%2,%3}, {%4,%5,%6,%7}, {%8,%9}, {%0,%1,%2,%3};"
                        : "+f"(acc[tm][tn0][0]), "+f"(acc[tm][tn0][1]),
                          "+f"(acc[tm][tn0][2]), "+f"(acc[tm][tn0][3])
                        : "r"(af[ab][tm][0]), "r"(af[ab][tm][1]),
                          "r"(af[ab][tm][2]), "r"(af[ab][tm][3]),
                          "r"(bq[buf][jj].x), "r"(bq[buf][jj].y));
                    asm volatile(
                        "mma.sync.aligned.m16n8k16.row.col.f32.f16.f16.f32 "
                        "{%0,%1,%2,%3}, {%4,%5,%6,%7}, {%8,%9}, {%0,%1,%2,%3};"
                        : "+f"(acc[tm][tn0 + 1][0]), "+f"(acc[tm][tn0 + 1][1]),
                          "+f"(acc[tm][tn0 + 1][2]), "+f"(acc[tm][tn0 + 1][3])
                        : "r"(af[ab][tm][0]), "r"(af[ab][tm][1]),
                          "r"(af[ab][tm][2]), "r"(af[ab][tm][3]),
                          "r"(bq[buf][jj].z), "r"(bq[buf][jj].w));
                }
        }

        // -------- epilogue at each ei boundary --------
        if ((g & 7) == 7) {
            const int ei = g >> 3;
            float lp[2][2] = {{0.f, 0.f}, {0.f, 0.f}};
            const int sg0 = s0 + warp_s * 32 + (lane >> 2);
            #pragma unroll
            for (int tm = 0; tm < 2; tm++) {
                const int srow = sg0 + tm * 16;
                #pragma unroll
                for (int tn = 0; tn < 8; tn++) {
                    const int e = ei * 128 + warp_e * 64 + tn * 8 + 2 * (lane & 3);
                    const float b0v = SM_BIAS(e), b1v = SM_BIAS(e + 1);
                    const float a0 = acc[tm][tn][0], a1 = acc[tm][tn][1];
                    const float a2 = acc[tm][tn][2], a3 = acc[tm][tn][3];
                    outr_b[(size_t)e       * S_DIM + srow]     = a0 + b0v;
                    outr_b[(size_t)(e + 1) * S_DIM + srow]     = a1 + b1v;
                    outr_b[(size_t)e       * S_DIM + srow + 8] = a2 + b0v;
                    outr_b[(size_t)(e + 1) * S_DIM + srow + 8] = a3 + b1v;
                    const float q0 = SM_QPB(e), q1 = SM_QPB(e + 1);
                    const float v0 = SM_V(e), v1 = SM_V(e + 1);
                    lp[tm][0] += tanha(q0 + a0) * v0 + tanha(q1 + a1) * v1;
                    lp[tm][1] += tanha(q0 + a2) * v0 + tanha(q1 + a3) * v1;
                    acc[tm][tn][0] = 0.f; acc[tm][tn][1] = 0.f;
                    acc[tm][tn][2] = 0.f; acc[tm][tn][3] = 0.f;
                }
            }
            #pragma unroll
            for (int tm = 0; tm < 2; tm++)
                #pragma unroll
                for (int h = 0; h < 2; h++) {
                    float v = lp[tm][h];
                    v += __shfl_xor_sync(0xffffffffu, v, 1);
                    v += __shfl_xor_sync(0xffffffffu, v, 2);
                    if ((lane & 3) == 0)
                        atomicAdd(&SM_L(warp_s * 32 + tm * 16 + h * 8 + (lane >> 2)), v);
                }
        }
    }

    __syncthreads();
    if (tid < BLK_S)
        out_logits[(size_t)b * S_DIM + s0 + tid] = 10.0f * tanha(SM_L(tid));
}

// ---------------------------------------------------------------------------
// launch
// ---------------------------------------------------------------------------
extern "C" void kernel_launch(void* const* d_in, const int* in_sizes, int n_in,
                              void* d_out, int out_size) {
    const float* query = (const float*)d_in[0];
    const float* ref   = (const float*)d_in[1];
    const float* Wq_w  = (const float*)d_in[2];
    const float* Wq_b  = (const float*)d_in[3];
    const float* Wr_w  = (const float*)d_in[4];
    const float* Wr_b  = (const float*)d_in[5];
    const float* value = (const float*)d_in[6];
    (void)in_sizes; (void)n_in; (void)out_size;

    float* out        = (float*)d_out;
    float* out_r      = out;                                   // [B, D, S]
    float* out_logits = out + (size_t)B_DIM * D_DIM * S_DIM;   // [B, S]

    prep_kernel<<<1280, 256>>>(Wr_w, query, Wq_w, Wq_b, Wr_b);

    const size_t smem = SMEM_WORDS * sizeof(float);
    cudaFuncSetAttribute(attn_main, cudaFuncAttributeMaxDynamicSharedMemorySize,
                         (int)smem);
    dim3 grid(S_DIM / BLK_S, B_DIM);
    attn_main<<<grid, NTHREADS, smem>>>(ref, Wr_b, value, out_r, out_logits);
}